// round 5
// baseline (speedup 1.0000x reference)
#include <cuda_runtime.h>
#include <cuda_bf16.h>
#include <mma.h>
#include <math.h>

using namespace nvcuda;

// ---------------- problem dims ----------------
#define BQ 8
#define NQ 896
#define MQ 512
#define ENF 3072
#define AAD 1280
#define HH 32
#define DD 64
#define INNER 2048
#define CTXD 256

#define SEQ_ROWS (BQ * NQ)   // 7168
#define AA_ROWS  (BQ * MQ)   // 4096

// ---------------- scratch (__device__ globals; no allocs allowed) ----------------
__device__ __nv_bfloat16 g_seq_e[(size_t)SEQ_ROWS * ENF];      // 44 MB
__device__ __nv_bfloat16 g_aa_e[(size_t)AA_ROWS * AAD];        // 10.5 MB
__device__ __nv_bfloat16 g_seq_w[(size_t)ENF * INNER];         // 12.6 MB
__device__ __nv_bfloat16 g_aa_w[(size_t)AAD * INNER];          // 5.2 MB
__device__ __nv_bfloat16 g_seq_lat[(size_t)BQ * HH * NQ * DD]; // 29.4 MB  [b][h][n][d]
__device__ __nv_bfloat16 g_aa_lat[(size_t)BQ * HH * MQ * DD];  // 16.8 MB  [b][h][j][d]
__device__ float g_inter[(size_t)BQ * NQ * HH];                // 0.92 MB  [b][n][h]
__device__ float g_v[BQ * HH];
__device__ int g_mask_mode;
__device__ unsigned char g_mask[BQ * MQ];

// ---------------- helpers ----------------
__device__ __forceinline__ void cp_async16(void* smem_dst, const void* gsrc) {
    unsigned int s = (unsigned int)__cvta_generic_to_shared(smem_dst);
    asm volatile("cp.async.cg.shared.global [%0], [%1], 16;\n" :: "r"(s), "l"(gsrc));
}
__device__ __forceinline__ void cp_commit() { asm volatile("cp.async.commit_group;\n"); }
template <int N>
__device__ __forceinline__ void cp_wait() { asm volatile("cp.async.wait_group %0;\n" :: "n"(N)); }

// ---------------- kernel 0: f32 -> bf16 convert (dst selected in-kernel) ----------------
__global__ void cvt_f32_bf16(const float4* __restrict__ src, int n4, int which) {
    uint2* dst = (which == 0) ? reinterpret_cast<uint2*>(g_seq_e)
               : (which == 1) ? reinterpret_cast<uint2*>(g_aa_e)
               : (which == 2) ? reinterpret_cast<uint2*>(g_seq_w)
                              : reinterpret_cast<uint2*>(g_aa_w);
    int i = blockIdx.x * blockDim.x + threadIdx.x;
    if (i < n4) {
        float4 f = src[i];
        __nv_bfloat162 lo = __floats2bfloat162_rn(f.x, f.y);
        __nv_bfloat162 hi = __floats2bfloat162_rn(f.z, f.w);
        uint2 u;
        u.x = *reinterpret_cast<unsigned int*>(&lo);
        u.y = *reinterpret_cast<unsigned int*>(&hi);
        dst[i] = u;
    }
}

// ---------------- mask dtype detect + canonicalize ----------------
__global__ void mask_detect(const unsigned int* __restrict__ m) {
    if (threadIdx.x != 0 || blockIdx.x != 0) return;
    int mode = 1;  // default: int32 {0,1}
    for (int i = 0; i < 1024; i++) {
        unsigned int v = m[i];
        if (v == 0x3F800000u) { mode = 2; break; }   // float32 1.0f
        if (v > 1u) { mode = 0; break; }             // packed bool bytes
    }
    g_mask_mode = mode;
}
__global__ void mask_canon(const void* __restrict__ src) {
    int i = blockIdx.x * blockDim.x + threadIdx.x;
    if (i >= BQ * MQ) return;
    int mode = g_mask_mode;
    unsigned char v;
    if (mode == 0)      v = ((const unsigned char*)src)[i] ? 1 : 0;
    else if (mode == 1) v = (((const int*)src)[i] != 0) ? 1 : 0;
    else                v = (((const float*)src)[i] != 0.0f) ? 1 : 0;
    g_mask[i] = v;
}

// ---------------- kernels 1&2: projection GEMM + bias + per-head l2norm ----------------
// C[row, col] = A[row, :K] @ W[:K, col] + bias; then l2norm over 64-col head groups.
// Block tile 128x128, BK=32, 256 threads (8 warps as 2x4), warp tile 64x32.
// Static smem only -> no cudaFuncSetAttribute needed.
#define GBM 128
#define GBN 128
#define GBK 32
#define GLDA 40    // 32 + 8 pad (bf16)
#define GLDB 136   // 128 + 8 pad (bf16)
#define GLDC 68    // 64 + 4 pad (fp32)
#define GEMM_SMEM_BYTES 37888  // max(A 20480 + B 17408 = 37888, C 128*68*4 = 34816)

__global__ void __launch_bounds__(256, 2)
proj_gemm_kernel(const float* __restrict__ bias, int which)  // which: 0=seq, 1=aa
{
    __shared__ __align__(16) unsigned char smem_raw[GEMM_SMEM_BYTES];
    __nv_bfloat16* As = reinterpret_cast<__nv_bfloat16*>(smem_raw);   // [2][128][GLDA]
    __nv_bfloat16* Bs = As + 2 * GBM * GLDA;                          // [2][32][GLDB]
    float* Cs = reinterpret_cast<float*>(smem_raw);                   // [128][GLDC] overlay

    const __nv_bfloat16* A = which ? g_aa_e : g_seq_e;
    const __nv_bfloat16* W = which ? g_aa_w : g_seq_w;
    __nv_bfloat16* outLat  = which ? g_aa_lat : g_seq_lat;
    const int K   = which ? AAD : ENF;
    const int rpb = which ? MQ : NQ;

    const int tid = threadIdx.x;
    const int wid = tid >> 5;
    const int warp_m = wid & 1;   // rows 64*warp_m
    const int warp_n = wid >> 1;  // cols 32*warp_n
    const int row0 = blockIdx.x * GBM;
    const int col0 = blockIdx.y * GBN;

    wmma::fragment<wmma::accumulator, 16, 16, 16, float> acc[4][2];
#pragma unroll
    for (int i = 0; i < 4; i++)
#pragma unroll
        for (int j = 0; j < 2; j++) wmma::fill_fragment(acc[i][j], 0.0f);

    const int nK = K / GBK;

    // stage loader: A tile 128x32 bf16 = 512 x 16B -> 2/thread; B tile 32x128 = 512 x 16B -> 2/thread
    {
#pragma unroll
        for (int i = 0; i < 2; i++) {
            int idx = tid + i * 256;
            int r = idx >> 2, kq = idx & 3;
            cp_async16(As + r * GLDA + kq * 8, A + (size_t)(row0 + r) * K + kq * 8);
        }
#pragma unroll
        for (int i = 0; i < 2; i++) {
            int idx = tid + i * 256;
            int r = idx >> 4, nq = idx & 15;
            cp_async16(Bs + r * GLDB + nq * 8, W + (size_t)r * INNER + col0 + nq * 8);
        }
        cp_commit();
    }

    for (int kt = 0; kt < nK; kt++) {
        int cur = kt & 1;
        if (kt + 1 < nK) {
            int nxt = cur ^ 1;
            int ktn = kt + 1;
#pragma unroll
            for (int i = 0; i < 2; i++) {
                int idx = tid + i * 256;
                int r = idx >> 2, kq = idx & 3;
                cp_async16(As + nxt * (GBM * GLDA) + r * GLDA + kq * 8,
                           A + (size_t)(row0 + r) * K + ktn * GBK + kq * 8);
            }
#pragma unroll
            for (int i = 0; i < 2; i++) {
                int idx = tid + i * 256;
                int r = idx >> 4, nq = idx & 15;
                cp_async16(Bs + nxt * (GBK * GLDB) + r * GLDB + nq * 8,
                           W + (size_t)(ktn * GBK + r) * INNER + col0 + nq * 8);
            }
            cp_commit();
            cp_wait<1>();
        } else {
            cp_wait<0>();
        }
        __syncthreads();

        const __nv_bfloat16* Ac = As + cur * (GBM * GLDA);
        const __nv_bfloat16* Bc = Bs + cur * (GBK * GLDB);
#pragma unroll
        for (int kk = 0; kk < GBK; kk += 16) {
            wmma::fragment<wmma::matrix_a, 16, 16, 16, __nv_bfloat16, wmma::row_major> af[4];
            wmma::fragment<wmma::matrix_b, 16, 16, 16, __nv_bfloat16, wmma::row_major> bf[2];
#pragma unroll
            for (int i = 0; i < 4; i++)
                wmma::load_matrix_sync(af[i], Ac + (warp_m * 64 + i * 16) * GLDA + kk, GLDA);
#pragma unroll
            for (int j = 0; j < 2; j++)
                wmma::load_matrix_sync(bf[j], Bc + kk * GLDB + warp_n * 32 + j * 16, GLDB);
#pragma unroll
            for (int i = 0; i < 4; i++)
#pragma unroll
                for (int j = 0; j < 2; j++)
                    wmma::mma_sync(acc[i][j], af[i], bf[j], acc[i][j]);
        }
        __syncthreads();
    }

    // ---- epilogue: bias + l2norm over each 64-col head group, two halves ----
    for (int nh = 0; nh < 2; nh++) {
        __syncthreads();
        if ((warp_n >> 1) == nh) {
            int jn = warp_n & 1;  // 0/1 within this 64-col half
#pragma unroll
            for (int i = 0; i < 4; i++)
#pragma unroll
                for (int j = 0; j < 2; j++)
                    wmma::store_matrix_sync(Cs + (warp_m * 64 + i * 16) * GLDC + jn * 32 + j * 16,
                                            acc[i][j], GLDC, wmma::mem_row_major);
        }
        __syncthreads();

        int r = tid >> 1, half = tid & 1;  // 2 threads per row, 32 cols each
        const float* crow = Cs + r * GLDC + half * 32;
        const float* brow = bias + col0 + nh * 64 + half * 32;
        float ss = 0.f;
#pragma unroll
        for (int c = 0; c < 32; c++) {
            float t = crow[c] + brow[c];
            ss += t * t;
        }
        ss += __shfl_xor_sync(0xffffffffu, ss, 1);
        float scale = 1.f / fmaxf(sqrtf(ss), 1e-12f);

        int gr = row0 + r;
        int b = gr / rpb, n = gr % rpb;
        int h = (col0 >> 6) + nh;
        __nv_bfloat16* op = outLat + ((size_t)(b * HH + h) * rpb + n) * DD + half * 32;
#pragma unroll
        for (int c8 = 0; c8 < 32; c8 += 8) {
            __nv_bfloat162 q[4];
#pragma unroll
            for (int t2 = 0; t2 < 4; t2++) {
                float v0 = (crow[c8 + 2 * t2] + brow[c8 + 2 * t2]) * scale;
                float v1 = (crow[c8 + 2 * t2 + 1] + brow[c8 + 2 * t2 + 1]) * scale;
                q[t2] = __floats2bfloat162_rn(v0, v1);
            }
            *reinterpret_cast<uint4*>(op + c8) = *reinterpret_cast<uint4*>(q);
        }
        __syncthreads();
    }
}

// ---------------- kernel 3: interaction scores + masked online logsumexp ----------------
// grid: (N/64 = 14, B*H = 256). block 256 threads. Per block: 64 i-rows, 8 j-chunks of 64.
#define ILDS 72   // 64 + 8 pad (bf16)
#define ILDC 68   // 64 + 4 pad (fp32)

__global__ void __launch_bounds__(256, 2)
inter_kernel()
{
    __shared__ __nv_bfloat16 Sseq[64 * ILDS];
    __shared__ __nv_bfloat16 Saa[64 * ILDS];
    __shared__ float Csm[64 * ILDC];
    __shared__ float m_run[64], s_run[64];
    __shared__ unsigned char msk[64];

    const int tid = threadIdx.x;
    const int wid = tid >> 5;
    const int itile = blockIdx.x;
    const int bh = blockIdx.y;
    const int b = bh >> 5;

    const __nv_bfloat16* seqp = g_seq_lat + (size_t)bh * NQ * DD + (size_t)itile * 64 * DD;
    const __nv_bfloat16* aap = g_aa_lat + (size_t)bh * MQ * DD;
    const unsigned char* mp = g_mask + b * MQ;

    // load seq tile: 64 x 64 bf16 = 512 x 16B
#pragma unroll
    for (int i = 0; i < 2; i++) {
        int idx = tid + i * 256;
        int r = idx >> 3, dq = idx & 7;
        *reinterpret_cast<uint4*>(Sseq + r * ILDS + dq * 8) =
            *reinterpret_cast<const uint4*>(seqp + r * DD + dq * 8);
    }
    if (tid < 64) { m_run[tid] = -INFINITY; s_run[tid] = 0.f; }

    const int warp_m = wid & 3;   // rows 16*warp_m
    const int warp_n = wid >> 2;  // cols 32*warp_n

    for (int jc = 0; jc < 8; jc++) {
        __syncthreads();

        // load aa chunk 64 x 64 bf16 + mask
#pragma unroll
        for (int i = 0; i < 2; i++) {
            int idx = tid + i * 256;
            int r = idx >> 3, dq = idx & 7;
            *reinterpret_cast<uint4*>(Saa + r * ILDS + dq * 8) =
                *reinterpret_cast<const uint4*>(aap + (size_t)(jc * 64 + r) * DD + dq * 8);
        }
        if (tid < 64) msk[tid] = mp[jc * 64 + tid];
        __syncthreads();

        wmma::fragment<wmma::accumulator, 16, 16, 16, float> acc[2];
        wmma::fill_fragment(acc[0], 0.f);
        wmma::fill_fragment(acc[1], 0.f);
#pragma unroll
        for (int kk = 0; kk < 64; kk += 16) {
            wmma::fragment<wmma::matrix_a, 16, 16, 16, __nv_bfloat16, wmma::row_major> af;
            wmma::load_matrix_sync(af, Sseq + (warp_m * 16) * ILDS + kk, ILDS);
#pragma unroll
            for (int j = 0; j < 2; j++) {
                wmma::fragment<wmma::matrix_b, 16, 16, 16, __nv_bfloat16, wmma::col_major> bfg;
                wmma::load_matrix_sync(bfg, Saa + (warp_n * 32 + j * 16) * ILDS + kk, ILDS);
                wmma::mma_sync(acc[j], af, bfg, acc[j]);
            }
        }
        wmma::store_matrix_sync(Csm + (warp_m * 16) * ILDC + warp_n * 32, acc[0], ILDC, wmma::mem_row_major);
        wmma::store_matrix_sync(Csm + (warp_m * 16) * ILDC + warp_n * 32 + 16, acc[1], ILDC, wmma::mem_row_major);
        __syncthreads();

        // online logsumexp partial update (4 threads per row, 16 cols each)
        int r = tid >> 2, part = tid & 3;
        float vals[16];
        float lmax = -INFINITY;
#pragma unroll
        for (int c = 0; c < 16; c++) {
            int j = part * 16 + c;
            float vv = msk[j] ? -3.402823466e38f : Csm[r * ILDC + j];
            vals[c] = vv;
            lmax = fmaxf(lmax, vv);
        }
        lmax = fmaxf(lmax, __shfl_xor_sync(0xffffffffu, lmax, 1));
        lmax = fmaxf(lmax, __shfl_xor_sync(0xffffffffu, lmax, 2));
        float m_old = m_run[r];
        float m_new = fmaxf(m_old, lmax);
        float lsum = 0.f;
#pragma unroll
        for (int c = 0; c < 16; c++) lsum += expf(vals[c] - m_new);
        lsum += __shfl_xor_sync(0xffffffffu, lsum, 1);
        lsum += __shfl_xor_sync(0xffffffffu, lsum, 2);
        if (part == 0) {
            s_run[r] = s_run[r] * expf(m_old - m_new) + lsum;
            m_run[r] = m_new;
        }
    }
    __syncthreads();

    if (tid < 64) {
        int i = itile * 64 + tid;
        g_inter[((size_t)b * NQ + i) * HH + (bh & 31)] = m_run[tid] + logf(s_run[tid]);
    }
}

// ---------------- kernel 4a: fold gating + pred_w into v[b][h] ----------------
__global__ void __launch_bounds__(1024)
gate_kernel(const float* __restrict__ ctx, const float* __restrict__ ctx_w,
            const float* __restrict__ ctx_b, const float* __restrict__ tlw,
            const float* __restrict__ pred_w)
{
    int b = blockIdx.x;
    int h = threadIdx.x >> 5, hp = threadIdx.x & 31;
    const float* cb = ctx + b * CTXD;
    int col = h * 32 + hp;
    float acc = 0.f;
#pragma unroll 8
    for (int k = 0; k < CTXD; k++) acc += cb[k] * ctx_w[k * (HH * HH) + col];
    float g = 1.f / (1.f + expf(-(acc + ctx_b[col])));
    float val = tlw[h * 32 + hp] * g * pred_w[hp];
#pragma unroll
    for (int o = 16; o; o >>= 1) val += __shfl_xor_sync(0xffffffffu, val, o);
    if (hp == 0) g_v[b * HH + h] = val;
}

// ---------------- kernel 4b: pred = softplus(inter . v + pred_b) ----------------
__global__ void pred_kernel(const float* __restrict__ pred_b, float* __restrict__ out)
{
    int idx = blockIdx.x * blockDim.x + threadIdx.x;
    if (idx >= SEQ_ROWS) return;
    int b = idx / NQ;
    const float* ip = g_inter + (size_t)idx * HH;
    const float* vp = g_v + b * HH;
    float x = pred_b[0];
#pragma unroll
    for (int hq = 0; hq < HH; hq++) x += ip[hq] * vp[hq];
    out[idx] = fmaxf(x, 0.f) + log1pf(expf(-fabsf(x)));
}

// ---------------- launch (kernel launches ONLY — graph-capture safe) ----------------
extern "C" void kernel_launch(void* const* d_in, const int* in_sizes, int n_in,
                              void* d_out, int out_size)
{
    const float* seq_embed = (const float*)d_in[0];
    const float* aa_embed  = (const float*)d_in[1];
    const float* ctx       = (const float*)d_in[2];
    const float* seq_b     = (const float*)d_in[4];
    const float* aa_b      = (const float*)d_in[6];
    const float* tlw       = (const float*)d_in[7];
    const float* ctx_w     = (const float*)d_in[8];
    const float* ctx_b     = (const float*)d_in[9];
    const float* pred_w    = (const float*)d_in[10];
    const float* pred_b    = (const float*)d_in[11];
    float* out = (float*)d_out;

    // 0) convert inputs/weights to bf16 (destinations are __device__ globals)
    {
        int n4;
        n4 = SEQ_ROWS * ENF / 4;
        cvt_f32_bf16<<<(n4 + 255) / 256, 256>>>((const float4*)seq_embed, n4, 0);
        n4 = AA_ROWS * AAD / 4;
        cvt_f32_bf16<<<(n4 + 255) / 256, 256>>>((const float4*)aa_embed, n4, 1);
        n4 = ENF * INNER / 4;
        cvt_f32_bf16<<<(n4 + 255) / 256, 256>>>((const float4*)d_in[3], n4, 2);
        n4 = AAD * INNER / 4;
        cvt_f32_bf16<<<(n4 + 255) / 256, 256>>>((const float4*)d_in[5], n4, 3);
    }

    // 0b) mask dtype detect + canonicalize
    mask_detect<<<1, 1>>>((const unsigned int*)d_in[12]);
    mask_canon<<<(BQ * MQ + 255) / 256, 256>>>(d_in[12]);

    // 1) seq projection + l2norm
    {
        dim3 grid(SEQ_ROWS / GBM, INNER / GBN);  // (56, 16)
        proj_gemm_kernel<<<grid, 256>>>(seq_b, 0);
    }
    // 2) aa projection + l2norm
    {
        dim3 grid(AA_ROWS / GBM, INNER / GBN);   // (32, 16)
        proj_gemm_kernel<<<grid, 256>>>(aa_b, 1);
    }
    // 3) interaction + masked logsumexp
    {
        dim3 grid(NQ / 64, BQ * HH);  // (14, 256)
        inter_kernel<<<grid, 256>>>();
    }
    // 4) gating fold + prediction
    gate_kernel<<<BQ, 1024>>>(ctx, ctx_w, ctx_b, tlw, pred_w);
    pred_kernel<<<(SEQ_ROWS + 255) / 256, 256>>>(pred_b, out);
}